// round 16
// baseline (speedup 1.0000x reference)
#include <cuda_runtime.h>
#include <cuda_bf16.h>
#include <cuda_fp16.h>
#include <math.h>

#define MTOT 8192
#define BGR  16
#define NATOM 512
#define FDIM 128
#define HID  64
#define DDIM 16
#define SEIN 95
#define EHIN 159
#define APB  8          // atoms per block in pair kernel
#define NBLK (MTOT/APB) // 1024
#define TABN 16384
#define TAB_LO 5.0f
#define TAB_HI 141.0f
#define FMT 16          // atoms per block in final kernels

__device__ float g_src[MTOT*DDIM];
__device__ float g_mean[BGR*DDIM];
__device__ float g_shell[MTOT*SEIN];
__device__ float g_ktab[TABN];
__device__ float g_emb[MTOT*DDIM];

__device__ __forceinline__ float siluf(float x){ return x * (1.f/(1.f + __expf(-x))); }

__device__ __forceinline__ float blockSum(float v, float* red, int nw){
  #pragma unroll
  for (int o=16;o>0;o>>=1) v += __shfl_xor_sync(0xffffffffu, v, o);
  if ((threadIdx.x&31)==0) red[threadIdx.x>>5]=v;
  __syncthreads();
  float s=0.f;
  for(int k=0;k<nw;k++) s += red[k];
  __syncthreads();
  return s;
}

// warp-cooperative LayerNorm of one smem row (stride 1), in/out may alias.
__device__ __forceinline__ void warpLN(const float* row, float* dst,
                                       const float* gv, const float* bv,
                                       int n, int lane, float invn){
  const unsigned full=0xffffffffu;
  float s=0.f;
  for(int k=lane;k<n;k+=32) s+=row[k];
  #pragma unroll
  for(int o=16;o;o>>=1) s+=__shfl_xor_sync(full,s,o);
  float m=s*invn;
  float q=0.f;
  for(int k=lane;k<n;k+=32){ float d=row[k]-m; q+=d*d; }
  #pragma unroll
  for(int o=16;o;o>>=1) q+=__shfl_xor_sync(full,q,o);
  float inv=rsqrtf(q*invn+1e-5f);
  for(int k=lane;k<n;k+=32) dst[k]=(row[k]-m)*inv*gv[k]+bv[k];
}

// ---------------- kernel 1: per-atom source features (+ zero out) + ktab tail blocks ----------------
__global__ void src_kernel(const float* __restrict__ x,
                           const float* __restrict__ lg, const float* __restrict__ lb,
                           const float* __restrict__ w1, const float* __restrict__ b1,
                           const float* __restrict__ w2, const float* __restrict__ b2,
                           const float* __restrict__ sg, const float* __restrict__ sb,
                           const float* __restrict__ kw1, const float* __restrict__ kb1,
                           const float* __restrict__ kw2, const float* __restrict__ kb2,
                           const float* __restrict__ kscr,
                           float* __restrict__ out, int out_n)
{
  __shared__ float sh[FDIM];
  __shared__ float red[4];
  __shared__ float hpart[FDIM];
  __shared__ float hp2[HID];
  __shared__ float hidsh[HID];
  int t=threadIdx.x;

  if(blockIdx.x >= MTOT){
    int i = (blockIdx.x - MTOT)*FDIM + t;
    if(i<TABN){
      float d = TAB_LO + (float)i * ((TAB_HI-TAB_LO)/(float)(TABN-1));
      float ks = kscr[0];
      float screening = (ks>20.f)? ks : log1pf(expf(ks));
      float base = expf(-screening*d)/d;
      float gin[10];
      gin[0]=d*0.2f; gin[1]=d*0.025f;
      #pragma unroll
      for(int k=0;k<8;k++){ float u=d-(5.f+5.f*(float)k); gin[2+k]=expf(-0.04f*u*u); }
      float outv = kb2[0];
      for(int h=0;h<32;h++){
        float a = kb1[h];
        #pragma unroll
        for(int f=0;f<10;f++) a += gin[f]*kw1[f*32+h];
        outv += (a*(1.f/(1.f+expf(-a)))) * kw2[h];
      }
      g_ktab[i] = base * (1.f + tanhf(outv));
    }
    return;
  }

  int atom=blockIdx.x;
  if(atom==0 && t<out_n) out[t]=0.f;
  float v = x[atom*FDIM+t];
  float m = blockSum(v,red,4)*(1.f/FDIM);
  float dv = v-m;
  float var = blockSum(dv*dv,red,4)*(1.f/FDIM);
  float hn = dv*rsqrtf(var+1e-5f)*lg[t]+lb[t];
  sh[t]=hn;
  __syncthreads();
  {
    int h=t&63, part=t>>6;
    float a = part ? 0.f : b1[h];
    int k0=part*64;
    #pragma unroll 8
    for(int k=k0;k<k0+64;k++) a += sh[k]*w1[k*HID+h];
    hpart[part*64+h]=a;
  }
  __syncthreads();
  if(t<HID) hidsh[t]=siluf(hpart[t]+hpart[64+t]);
  __syncthreads();
  if(t<64){
    int d=t&15, part=t>>4;
    float a = part ? 0.f : b2[d];
    int k0=part*16;
    #pragma unroll
    for(int k=k0;k<k0+16;k++) a += hidsh[k]*w2[k*DDIM+d];
    hp2[part*16+d]=a;
  }
  __syncthreads();
  if(t<DDIM){
    float vv=hp2[t]+hp2[16+t]+hp2[32+t]+hp2[48+t];
    float s=vv;
    #pragma unroll
    for(int o=8;o;o>>=1) s+=__shfl_xor_sync(0xffffu,s,o);
    float mm=s*(1.f/DDIM);
    float d=vv-mm; float q=d*d;
    #pragma unroll
    for(int o=8;o;o>>=1) q+=__shfl_xor_sync(0xffffu,q,o);
    float vr=q*(1.f/DDIM);
    g_src[atom*DDIM+t]=d*rsqrtf(vr+1e-5f)*sg[t]+sb[t];
  }
}

// ---------------- kernel 2: per-graph source mean ----------------
__global__ void mean_kernel(){
  int g=blockIdx.x, t=threadIdx.x;
  float acc[DDIM];
  #pragma unroll
  for(int c=0;c<DDIM;c++) acc[c]=0.f;
  for(int a=t;a<NATOM;a+=256){
    const float* p=&g_src[(g*NATOM+a)*DDIM];
    #pragma unroll
    for(int c=0;c<DDIM;c++) acc[c]+=p[c];
  }
  __shared__ float red[DDIM];
  if(t<DDIM) red[t]=0.f;
  __syncthreads();
  #pragma unroll
  for(int c=0;c<DDIM;c++){
    float s=acc[c];
    #pragma unroll
    for(int o=16;o;o>>=1) s+=__shfl_xor_sync(0xffffffffu,s,o);
    if((t&31)==0) atomicAdd(&red[c],s);
  }
  __syncthreads();
  if(t<DDIM) g_mean[g*DDIM+t]=red[t]*(1.f/NATOM);
}

// ---------------- kernel 3: pair loop + shell statistics (ballot-compacted) ----------------
__global__ void __launch_bounds__(256)
pair_kernel(const float* __restrict__ pos)
{
  extern __shared__ float smem[];
  float* px   = smem;                      // 512 f
  float* py   = px+NATOM;                  // 512 f
  float* pz   = py+NATOM;                  // 512 f
  __half* ssh = (__half*)(pz+NATOM);       // 512*16 half (16KB)
  float* ckvb = (float*)(ssh + NATOM*DDIM);// 8*512 f compacted (kerv|j)

  int t=threadIdx.x;
  int blk=blockIdx.x;
  int g = blk/(NATOM/APB);
  int ibase = (blk%(NATOM/APB))*APB;

  for(int a=t;a<NATOM;a+=256){
    int ga=g*NATOM+a;
    px[a]=pos[ga*3+0]; py[a]=pos[ga*3+1]; pz[a]=pos[ga*3+2];
  }
  for(int idx=t; idx<NATOM*DDIM; idx+=256){
    int a=idx>>4, c=idx&15;
    ssh[idx]=__float2half(g_src[(g*NATOM+a)*DDIM+c]-g_mean[g*DDIM+c]);
  }
  __syncthreads();

  int w=t>>5, lane=t&31;
  int il=ibase+w;
  float xi=px[il], yi=py[il], zi=pz[il];
  float* ckv=ckvb+w*NATOM;
  const unsigned full=0xffffffffu;
  const unsigned lt=(1u<<lane)-1u;

  int   cnt[5]={0,0,0,0,0};
  float sr[5]={0,0,0,0,0}, sr2[5]={0,0,0,0,0};

  #pragma unroll 4
  for(int it=0;it<16;it++){
    int j=lane+it*32;
    float dx=xi-px[j], dy=yi-py[j], dz=zi-pz[j];
    float d2=dx*dx+dy*dy+dz*dz+1e-12f;
    float d=__fsqrt_rn(d2);
    int sidx=5;
    if(j!=il && d>=5.0f)
      sidx=(d<10.f)?0:((d<20.f)?1:((d<40.f)?2:((d<80.f)?3:4)));
    #pragma unroll
    for(int s=0;s<5;s++){
      unsigned m=__ballot_sync(full, sidx==s);
      cnt[s]+=__popc(m);
      if(sidx==s){ sr[s]+=d; sr2[s]+=d2; }
    }
  }
  int base[5]; { int run=0;
    #pragma unroll
    for(int s=0;s<5;s++){ base[s]=run; run+=cnt[s]; } }

  const float tscale = (float)(TABN-1)/(TAB_HI-TAB_LO);

  #pragma unroll 2
  for(int it=0;it<16;it++){
    int j=lane+it*32;
    float dx=xi-px[j], dy=yi-py[j], dz=zi-pz[j];
    float d2=dx*dx+dy*dy+dz*dz+1e-12f;
    float d=__fsqrt_rn(d2);
    int sidx=5;
    if(j!=il && d>=5.0f)
      sidx=(d<10.f)?0:((d<20.f)?1:((d<40.f)?2:((d<80.f)?3:4)));
    float kerv=0.f;
    if(sidx<5){
      float u=(d-TAB_LO)*tscale;
      u=fminf(u,(float)(TABN-1)-1e-3f);
      int i0=(int)u; float fr=u-(float)i0;
      float t0=__ldg(&g_ktab[i0]), t1=__ldg(&g_ktab[i0+1]);
      kerv=fmaf(fr,t1-t0,t0);
    }
    #pragma unroll
    for(int s=0;s<5;s++){
      unsigned m=__ballot_sync(full, sidx==s);
      if(sidx==s){
        int p=base[s]+__popc(m&lt);
        ckv[p]=__uint_as_float((__float_as_uint(kerv)&~511u)|(unsigned)j);
      }
      base[s]+=__popc(m);
    }
  }
  __syncwarp();

  int ig=g*NATOM+il;
  float* outp=&g_shell[ig*SEIN];
  int chgrp=lane&3, jsub=lane>>2;

  int e0=0;
  #pragma unroll
  for(int q=0;q<5;q++){
    float4 acc=make_float4(0.f,0.f,0.f,0.f);
    int e1=e0+cnt[q];
    for(int e=e0+jsub;e<e1;e+=8){
      unsigned pk=__float_as_uint(ckv[e]);
      int j=(int)(pk&511u);
      float kv=__uint_as_float(pk&~511u);
      float2 raw=*((const float2*)(ssh + j*DDIM) + chgrp);
      __half2 h0=*(__half2*)&raw.x;
      __half2 h1=*(__half2*)&raw.y;
      float2 c0=__half22float2(h0);
      float2 c1=__half22float2(h1);
      acc.x=fmaf(kv,c0.x,acc.x);
      acc.y=fmaf(kv,c0.y,acc.y);
      acc.z=fmaf(kv,c1.x,acc.z);
      acc.w=fmaf(kv,c1.y,acc.w);
    }
    e0=e1;
    #pragma unroll
    for(int o=4;o<32;o<<=1){
      acc.x+=__shfl_xor_sync(full,acc.x,o);
      acc.y+=__shfl_xor_sync(full,acc.y,o);
      acc.z+=__shfl_xor_sync(full,acc.z,o);
      acc.w+=__shfl_xor_sync(full,acc.w,o);
    }
    if(lane<4){
      float inv=1.f/fmaxf((float)cnt[q],1.f);
      outp[q*19+chgrp*4+0]=acc.x*inv;
      outp[q*19+chgrp*4+1]=acc.y*inv;
      outp[q*19+chgrp*4+2]=acc.z*inv;
      outp[q*19+chgrp*4+3]=acc.w*inv;
    }
  }

  #pragma unroll
  for(int q=0;q<5;q++){
    #pragma unroll
    for(int o=16;o;o>>=1){
      sr [q]+=__shfl_xor_sync(full,sr [q],o);
      sr2[q]+=__shfl_xor_sync(full,sr2[q],o);
    }
  }
  if(lane==16){
    #pragma unroll
    for(int q=0;q<5;q++) outp[q*19+16]=(float)cnt[q];
  } else if(lane==17){
    #pragma unroll
    for(int q=0;q<5;q++) outp[q*19+17]=sr[q]/fmaxf((float)cnt[q],1.f);
  } else if(lane==18){
    #pragma unroll
    for(int q=0;q<5;q++) outp[q*19+18]=__fsqrt_rn(sr2[q]/fmaxf((float)cnt[q],1.f)+1e-12f);
  }
}

// ---------------- kernel 5a: shell LN + GEMM1 + emb (fp32 weights, float4 k-loop) ----------------
// smem: w1s[96*64] zero-padded row95 | w2s[64*16] | shn[16*96] | hid[16*68] | params
#define A_W1   0
#define A_W2   (A_W1+96*64)
#define A_SHN  (A_W2+64*16)
#define A_HID  (A_SHN+16*96)
#define A_LNG  (A_HID+16*68)
#define A_LNB  (A_LNG+96)
#define A_B1   (A_LNB+96)
#define A_B2   (A_B1+64)
#define A_SMEM ((A_B2+16)*4)

__global__ void __launch_bounds__(256)
final_a(const float* __restrict__ selng, const float* __restrict__ selnb,
        const float* __restrict__ sew1,  const float* __restrict__ seb1,
        const float* __restrict__ sew2,  const float* __restrict__ seb2)
{
  extern __shared__ float fs[];
  float* w1s=fs+A_W1;
  float* w2s=fs+A_W2;
  float* shn=fs+A_SHN;   // stride 96 (16B aligned)
  float* hid=fs+A_HID;   // stride 68 (16B aligned)

  int t=threadIdx.x;
  int abase=blockIdx.x*FMT;

  for(int i=t;i<SEIN*HID;i+=256) w1s[i]=sew1[i];
  for(int i=t;i<HID;i+=256){}    // (no-op)
  if(t<HID) { w1s[95*64+t]=0.f; } // zero-pad k=95 row
  for(int i=t;i<HID*DDIM;i+=256) w2s[i]=sew2[i];
  if(t<SEIN){ fs[A_LNG+t]=selng[t]; fs[A_LNB+t]=selnb[t]; }
  if(t<HID) fs[A_B1+t]=seb1[t];
  if(t<DDIM) fs[A_B2+t]=seb2[t];
  __syncthreads();

  int w=t>>5, lane=t&31;

  // LN(shell) from registers (no rsh staging): 8 warps x 2 atoms
  #pragma unroll
  for(int a2=0;a2<2;a2++){
    int a=w*2+a2;
    const float* sp=&g_shell[(abase+a)*SEIN];
    float v0=sp[lane];
    float v1=sp[lane+32];
    float v2=(lane<31)? sp[lane+64] : 0.f;
    float s=v0+v1+v2;
    const unsigned full=0xffffffffu;
    #pragma unroll
    for(int o=16;o;o>>=1) s+=__shfl_xor_sync(full,s,o);
    float m=s*(1.f/SEIN);
    float d0=v0-m, d1=v1-m, d2=(lane<31)?(v2-m):0.f;
    float q=d0*d0+d1*d1+d2*d2;
    #pragma unroll
    for(int o=16;o;o>>=1) q+=__shfl_xor_sync(full,q,o);
    float inv=rsqrtf(q*(1.f/SEIN)+1e-5f);
    float* dst=shn+a*96;
    dst[lane]    =d0*inv*fs[A_LNG+lane]+fs[A_LNB+lane];
    dst[lane+32] =d1*inv*fs[A_LNG+lane+32]+fs[A_LNB+lane+32];
    if(lane<31) dst[lane+64]=d2*inv*fs[A_LNG+lane+64]+fs[A_LNB+lane+64];
    if(lane==31) dst[95]=0.f;   // pad
  }
  __syncthreads();

  // GEMM1: hid[16][64] = silu(shn @ w1 + b1); thread=(a=t>>4, tx=t&15); K=96 via float4
  {
    int tx=t&15, a=t>>4;
    float acc0,acc1,acc2,acc3;
    acc0=fs[A_B1+tx*4+0]; acc1=fs[A_B1+tx*4+1];
    acc2=fs[A_B1+tx*4+2]; acc3=fs[A_B1+tx*4+3];
    const float4* w4=(const float4*)w1s;
    const float4* A4=(const float4*)(shn+a*96);
    #pragma unroll
    for(int kg=0;kg<24;kg++){
      float4 av=A4[kg];
      float4 w0=w4[(4*kg+0)*16+tx];
      float4 w1v=w4[(4*kg+1)*16+tx];
      float4 w2v=w4[(4*kg+2)*16+tx];
      float4 w3v=w4[(4*kg+3)*16+tx];
      acc0=fmaf(av.x,w0.x,acc0); acc1=fmaf(av.x,w0.y,acc1);
      acc2=fmaf(av.x,w0.z,acc2); acc3=fmaf(av.x,w0.w,acc3);
      acc0=fmaf(av.y,w1v.x,acc0); acc1=fmaf(av.y,w1v.y,acc1);
      acc2=fmaf(av.y,w1v.z,acc2); acc3=fmaf(av.y,w1v.w,acc3);
      acc0=fmaf(av.z,w2v.x,acc0); acc1=fmaf(av.z,w2v.y,acc1);
      acc2=fmaf(av.z,w2v.z,acc2); acc3=fmaf(av.z,w2v.w,acc3);
      acc0=fmaf(av.w,w3v.x,acc0); acc1=fmaf(av.w,w3v.y,acc1);
      acc2=fmaf(av.w,w3v.z,acc2); acc3=fmaf(av.w,w3v.w,acc3);
    }
    float* H=hid+a*68+tx*4;
    H[0]=siluf(acc0); H[1]=siluf(acc1); H[2]=siluf(acc2); H[3]=siluf(acc3);
  }
  __syncthreads();

  // emb[16][16] = hid @ w2 + b2 -> g_emb; thread=(a=t>>4, c=t&15)
  {
    int a=t>>4, c=t&15;
    float acc=fs[A_B2+c];
    const float4* H4=(const float4*)(hid+a*68);
    #pragma unroll
    for(int kg=0;kg<16;kg++){
      float4 hv=H4[kg];
      acc=fmaf(hv.x,w2s[(4*kg+0)*16+c],acc);
      acc=fmaf(hv.y,w2s[(4*kg+1)*16+c],acc);
      acc=fmaf(hv.z,w2s[(4*kg+2)*16+c],acc);
      acc=fmaf(hv.w,w2s[(4*kg+3)*16+c],acc);
    }
    g_emb[(abase+a)*DDIM+c]=acc;
  }
}

// ---------------- kernel 5b: ein build + LN + GEMM2 + energy head ----------------
// smem: ew1s[160*64] zero-padded row159 | ein[16*164] | srcs[16*16] | embs[16*16] | params
#define B_EW1  0
#define B_EIN  (B_EW1+160*64)
#define B_SRC  (B_EIN+16*164)
#define B_EMB  (B_SRC+16*16)
#define B_EW2  (B_EMB+16*16)
#define B_LNG  (B_EW2+64)
#define B_LNB  (B_LNG+160)
#define B_EB1  (B_LNB+160)
#define B_SMEM ((B_EB1+64)*4)

__global__ void __launch_bounds__(256)
final_b(const int* __restrict__ batch,
        const float* __restrict__ ehlng, const float* __restrict__ ehlnb,
        const float* __restrict__ ehw1,  const float* __restrict__ ehb1,
        const float* __restrict__ ehw2,  const float* __restrict__ ehb2,
        const float* __restrict__ fg, const float* __restrict__ es, float* out)
{
  extern __shared__ float fs[];
  float* ew1s=fs+B_EW1;
  float* ein =fs+B_EIN;   // stride 164 (16B aligned)
  float* srcs=fs+B_SRC;
  float* embs=fs+B_EMB;
  float* h2  =fs+B_EIN;   // aliases ein after GEMM2 reads complete (stride 68)

  int t=threadIdx.x;
  int abase=blockIdx.x*FMT;
  int g=abase/NATOM;

  for(int i=t;i<EHIN*HID;i+=256) ew1s[i]=ehw1[i];
  if(t<HID) ew1s[159*64+t]=0.f;   // zero-pad k=159 row
  if(t<HID){ fs[B_EW2+t]=ehw2[t]; fs[B_EB1+t]=ehb1[t]; }
  if(t<EHIN){ fs[B_LNG+t]=ehlng[t]; fs[B_LNB+t]=ehlnb[t]; }
  for(int i=t;i<FMT*DDIM;i+=256){
    int a=i>>4, c=i&15;
    srcs[i]=g_src[(abase+a)*DDIM+c]-g_mean[g*DDIM+c];
    embs[i]=g_emb[(abase+a)*DDIM+c];
  }
  __syncthreads();

  // build ein[16][160] (pad [159]=0 handled by e==159 case; stride 164)
  for(int i=t;i<FMT*160;i+=256){
    int a=i/160, e=i-a*160;
    float v;
    if(e<16){ v=srcs[a*16+e]; }
    else if(e<32){ v=embs[a*16+(e-16)]; }
    else if(e<48){ v=srcs[a*16+(e-32)]*embs[a*16+(e-32)]; }
    else if(e<64){ v=srcs[a*16+(e-48)]-embs[a*16+(e-48)]; }
    else if(e<159){ v=g_shell[(abase+a)*SEIN+(e-64)]; }
    else { v=0.f; }
    ein[a*164+e]=v;
  }
  __syncthreads();

  int w=t>>5, lane=t&31;

  // LN(ein) in place over 159 entries (pad at 159 untouched = 0)
  #pragma unroll
  for(int a2=0;a2<2;a2++){
    int a=w*2+a2;
    warpLN(ein+a*164, ein+a*164, fs+B_LNG, fs+B_LNB, EHIN, lane, 1.f/EHIN);
  }
  __syncthreads();

  // GEMM2: h2[16][64] = silu(ein @ ew1 + eb1); K=160 via float4
  {
    int tx=t&15, a=t>>4;
    float acc0,acc1,acc2,acc3;
    acc0=fs[B_EB1+tx*4+0]; acc1=fs[B_EB1+tx*4+1];
    acc2=fs[B_EB1+tx*4+2]; acc3=fs[B_EB1+tx*4+3];
    const float4* w4=(const float4*)ew1s;
    const float4* A4=(const float4*)(ein+a*164);
    #pragma unroll
    for(int kg=0;kg<40;kg++){
      float4 av=A4[kg];
      float4 w0=w4[(4*kg+0)*16+tx];
      float4 w1v=w4[(4*kg+1)*16+tx];
      float4 w2v=w4[(4*kg+2)*16+tx];
      float4 w3v=w4[(4*kg+3)*16+tx];
      acc0=fmaf(av.x,w0.x,acc0); acc1=fmaf(av.x,w0.y,acc1);
      acc2=fmaf(av.x,w0.z,acc2); acc3=fmaf(av.x,w0.w,acc3);
      acc0=fmaf(av.y,w1v.x,acc0); acc1=fmaf(av.y,w1v.y,acc1);
      acc2=fmaf(av.y,w1v.z,acc2); acc3=fmaf(av.y,w1v.w,acc3);
      acc0=fmaf(av.z,w2v.x,acc0); acc1=fmaf(av.z,w2v.y,acc1);
      acc2=fmaf(av.z,w2v.z,acc2); acc3=fmaf(av.z,w2v.w,acc3);
      acc0=fmaf(av.w,w3v.x,acc0); acc1=fmaf(av.w,w3v.y,acc1);
      acc2=fmaf(av.w,w3v.z,acc2); acc3=fmaf(av.w,w3v.w,acc3);
    }
    __syncthreads();   // all ein reads done before h2 (aliases ein) written
    float* H=h2+a*68+tx*4;
    H[0]=siluf(acc0); H[1]=siluf(acc1); H[2]=siluf(acc2); H[3]=siluf(acc3);
  }
  __syncthreads();

  float scale = tanhf(fg[0])*__expf(es[0]);
  float eb2 = ehb2[0];
  #pragma unroll
  for(int a2=0;a2<2;a2++){
    int a=w*2+a2;
    float p=h2[a*68+lane]*fs[B_EW2+lane]+h2[a*68+lane+32]*fs[B_EW2+lane+32];
    #pragma unroll
    for(int o=16;o;o>>=1) p+=__shfl_xor_sync(0xffffffffu,p,o);
    if(lane==0){
      float pa=(p+eb2)*scale;
      atomicAdd(&out[batch[abase+a]],pa);
    }
  }
}

extern "C" void kernel_launch(void* const* d_in, const int* in_sizes, int n_in,
                              void* d_out, int out_size) {
  const float* x   = (const float*)d_in[0];
  const float* pos = (const float*)d_in[1];
  const int* batch = (const int*)d_in[2];
  int off = (in_sizes[3]==1) ? 4 : 3;
  const float* in_ln_g = (const float*)d_in[off+0];
  const float* in_ln_b = (const float*)d_in[off+1];
  const float* src_w1  = (const float*)d_in[off+2];
  const float* src_b1  = (const float*)d_in[off+3];
  const float* src_w2  = (const float*)d_in[off+4];
  const float* src_b2  = (const float*)d_in[off+5];
  const float* src_ln_g= (const float*)d_in[off+6];
  const float* src_ln_b= (const float*)d_in[off+7];
  const float* se_ln_g = (const float*)d_in[off+8];
  const float* se_ln_b = (const float*)d_in[off+9];
  const float* se_w1   = (const float*)d_in[off+10];
  const float* se_b1   = (const float*)d_in[off+11];
  const float* se_w2   = (const float*)d_in[off+12];
  const float* se_b2   = (const float*)d_in[off+13];
  const float* eh_ln_g = (const float*)d_in[off+14];
  const float* eh_ln_b = (const float*)d_in[off+15];
  const float* eh_w1   = (const float*)d_in[off+16];
  const float* eh_b1   = (const float*)d_in[off+17];
  const float* eh_w2   = (const float*)d_in[off+18];
  const float* eh_b2   = (const float*)d_in[off+19];
  const float* k_screen= (const float*)d_in[off+20];
  const float* kg_w1   = (const float*)d_in[off+21];
  const float* kg_b1   = (const float*)d_in[off+22];
  const float* kg_w2   = (const float*)d_in[off+23];
  const float* kg_b2   = (const float*)d_in[off+24];
  const float* far_gate= (const float*)d_in[off+25];
  const float* en_scale= (const float*)d_in[off+26];
  float* out = (float*)d_out;

  const int pair_smem = (3*NATOM)*4 + NATOM*DDIM*2 + APB*NATOM*4; // 38912B
  cudaFuncSetAttribute(pair_kernel, cudaFuncAttributeMaxDynamicSharedMemorySize, pair_smem);
  cudaFuncSetAttribute(final_a, cudaFuncAttributeMaxDynamicSharedMemorySize, A_SMEM);
  cudaFuncSetAttribute(final_b, cudaFuncAttributeMaxDynamicSharedMemorySize, B_SMEM);

  src_kernel<<<MTOT + TABN/FDIM, FDIM>>>(x, in_ln_g, in_ln_b, src_w1, src_b1, src_w2,
                            src_b2, src_ln_g, src_ln_b,
                            kg_w1, kg_b1, kg_w2, kg_b2, k_screen, out, out_size);
  mean_kernel<<<BGR,256>>>();
  pair_kernel<<<NBLK,256,pair_smem>>>(pos);
  final_a<<<MTOT/FMT,256,A_SMEM>>>(se_ln_g, se_ln_b, se_w1, se_b1, se_w2, se_b2);
  final_b<<<MTOT/FMT,256,B_SMEM>>>(batch, eh_ln_g, eh_ln_b, eh_w1, eh_b1, eh_w2, eh_b2,
                                   far_gate, en_scale, out);
}

// round 17
// speedup vs baseline: 1.1046x; 1.1046x over previous
#include <cuda_runtime.h>
#include <cuda_bf16.h>
#include <cuda_fp16.h>
#include <math.h>

#define MTOT 8192
#define BGR  16
#define NATOM 512
#define FDIM 128
#define HID  64
#define DDIM 16
#define SEIN 95
#define EHIN 159
#define APB  8          // atoms per block in pair kernel
#define NBLK (MTOT/APB) // 1024
#define TABN 16384
#define TAB_LO 5.0f
#define TAB_HI 141.0f
#define FMT 16          // atoms per block in final kernel

__device__ float g_src[MTOT*DDIM];
__device__ float g_mean[BGR*DDIM];
__device__ float g_shell[MTOT*SEIN];
__device__ float g_ktab[TABN];

__device__ __forceinline__ float siluf(float x){ return x * (1.f/(1.f + __expf(-x))); }

__device__ __forceinline__ float blockSum(float v, float* red, int nw){
  #pragma unroll
  for (int o=16;o>0;o>>=1) v += __shfl_xor_sync(0xffffffffu, v, o);
  if ((threadIdx.x&31)==0) red[threadIdx.x>>5]=v;
  __syncthreads();
  float s=0.f;
  for(int k=0;k<nw;k++) s += red[k];
  __syncthreads();
  return s;
}

// warp-cooperative LayerNorm of one smem row (stride 1), in/out may alias.
__device__ __forceinline__ void warpLN(const float* row, float* dst,
                                       const float* gv, const float* bv,
                                       int n, int lane, float invn){
  const unsigned full=0xffffffffu;
  float s=0.f;
  for(int k=lane;k<n;k+=32) s+=row[k];
  #pragma unroll
  for(int o=16;o;o>>=1) s+=__shfl_xor_sync(full,s,o);
  float m=s*invn;
  float q=0.f;
  for(int k=lane;k<n;k+=32){ float d=row[k]-m; q+=d*d; }
  #pragma unroll
  for(int o=16;o;o>>=1) q+=__shfl_xor_sync(full,q,o);
  float inv=rsqrtf(q*invn+1e-5f);
  for(int k=lane;k<n;k+=32) dst[k]=(row[k]-m)*inv*gv[k]+bv[k];
}

// ---------------- kernel 1: per-atom source features (+ zero out) + ktab tail blocks ----------------
__global__ void src_kernel(const float* __restrict__ x,
                           const float* __restrict__ lg, const float* __restrict__ lb,
                           const float* __restrict__ w1, const float* __restrict__ b1,
                           const float* __restrict__ w2, const float* __restrict__ b2,
                           const float* __restrict__ sg, const float* __restrict__ sb,
                           const float* __restrict__ kw1, const float* __restrict__ kb1,
                           const float* __restrict__ kw2, const float* __restrict__ kb2,
                           const float* __restrict__ kscr,
                           float* __restrict__ out, int out_n)
{
  __shared__ float sh[FDIM];
  __shared__ float red[4];
  __shared__ float hpart[FDIM];
  __shared__ float hp2[HID];
  __shared__ float hidsh[HID];
  int t=threadIdx.x;

  if(blockIdx.x >= MTOT){
    int i = (blockIdx.x - MTOT)*FDIM + t;
    if(i<TABN){
      float d = TAB_LO + (float)i * ((TAB_HI-TAB_LO)/(float)(TABN-1));
      float ks = kscr[0];
      float screening = (ks>20.f)? ks : log1pf(expf(ks));
      float base = expf(-screening*d)/d;
      float gin[10];
      gin[0]=d*0.2f; gin[1]=d*0.025f;
      #pragma unroll
      for(int k=0;k<8;k++){ float u=d-(5.f+5.f*(float)k); gin[2+k]=expf(-0.04f*u*u); }
      float outv = kb2[0];
      for(int h=0;h<32;h++){
        float a = kb1[h];
        #pragma unroll
        for(int f=0;f<10;f++) a += gin[f]*kw1[f*32+h];
        outv += (a*(1.f/(1.f+expf(-a)))) * kw2[h];
      }
      g_ktab[i] = base * (1.f + tanhf(outv));
    }
    return;
  }

  int atom=blockIdx.x;
  if(atom==0 && t<out_n) out[t]=0.f;
  float v = x[atom*FDIM+t];
  float m = blockSum(v,red,4)*(1.f/FDIM);
  float dv = v-m;
  float var = blockSum(dv*dv,red,4)*(1.f/FDIM);
  float hn = dv*rsqrtf(var+1e-5f)*lg[t]+lb[t];
  sh[t]=hn;
  __syncthreads();
  {
    int h=t&63, part=t>>6;
    float a = part ? 0.f : b1[h];
    int k0=part*64;
    #pragma unroll 8
    for(int k=k0;k<k0+64;k++) a += sh[k]*w1[k*HID+h];
    hpart[part*64+h]=a;
  }
  __syncthreads();
  if(t<HID) hidsh[t]=siluf(hpart[t]+hpart[64+t]);
  __syncthreads();
  if(t<64){
    int d=t&15, part=t>>4;
    float a = part ? 0.f : b2[d];
    int k0=part*16;
    #pragma unroll
    for(int k=k0;k<k0+16;k++) a += hidsh[k]*w2[k*DDIM+d];
    hp2[part*16+d]=a;
  }
  __syncthreads();
  if(t<DDIM){
    float vv=hp2[t]+hp2[16+t]+hp2[32+t]+hp2[48+t];
    float s=vv;
    #pragma unroll
    for(int o=8;o;o>>=1) s+=__shfl_xor_sync(0xffffu,s,o);
    float mm=s*(1.f/DDIM);
    float d=vv-mm; float q=d*d;
    #pragma unroll
    for(int o=8;o;o>>=1) q+=__shfl_xor_sync(0xffffu,q,o);
    float vr=q*(1.f/DDIM);
    g_src[atom*DDIM+t]=d*rsqrtf(vr+1e-5f)*sg[t]+sb[t];
  }
}

// ---------------- kernel 2: per-graph source mean ----------------
__global__ void mean_kernel(){
  int g=blockIdx.x, t=threadIdx.x;
  float acc[DDIM];
  #pragma unroll
  for(int c=0;c<DDIM;c++) acc[c]=0.f;
  for(int a=t;a<NATOM;a+=256){
    const float* p=&g_src[(g*NATOM+a)*DDIM];
    #pragma unroll
    for(int c=0;c<DDIM;c++) acc[c]+=p[c];
  }
  __shared__ float red[DDIM];
  if(t<DDIM) red[t]=0.f;
  __syncthreads();
  #pragma unroll
  for(int c=0;c<DDIM;c++){
    float s=acc[c];
    #pragma unroll
    for(int o=16;o;o>>=1) s+=__shfl_xor_sync(0xffffffffu,s,o);
    if((t&31)==0) atomicAdd(&red[c],s);
  }
  __syncthreads();
  if(t<DDIM) g_mean[g*DDIM+t]=red[t]*(1.f/NATOM);
}

// ---------------- kernel 3: pair loop + shell statistics ----------------
// Sweep A: distance + table-lerp ONCE, packed (kerv|sidx) cached in 16 registers;
//          counts via per-lane counters + warp shuffle reduce (uniform).
// Sweep B: pure ballot/scatter of cached values, grouped by shell.
// Pass 2:  per-shell tight LDS.64 -> 4 FFMA segments.
__global__ void __launch_bounds__(256)
pair_kernel(const float* __restrict__ pos)
{
  extern __shared__ float smem[];
  float* px   = smem;                      // 512 f
  float* py   = px+NATOM;                  // 512 f
  float* pz   = py+NATOM;                  // 512 f
  __half* ssh = (__half*)(pz+NATOM);       // 512*16 half (16KB)
  float* ckvb = (float*)(ssh + NATOM*DDIM);// 8*512 f compacted (kerv|j)

  int t=threadIdx.x;
  int blk=blockIdx.x;
  int g = blk/(NATOM/APB);
  int ibase = (blk%(NATOM/APB))*APB;

  for(int a=t;a<NATOM;a+=256){
    int ga=g*NATOM+a;
    px[a]=pos[ga*3+0]; py[a]=pos[ga*3+1]; pz[a]=pos[ga*3+2];
  }
  for(int idx=t; idx<NATOM*DDIM; idx+=256){
    int a=idx>>4, c=idx&15;
    ssh[idx]=__float2half(g_src[(g*NATOM+a)*DDIM+c]-g_mean[g*DDIM+c]);
  }
  __syncthreads();

  int w=t>>5, lane=t&31;
  int il=ibase+w;
  float xi=px[il], yi=py[il], zi=pz[il];
  float* ckv=ckvb+w*NATOM;
  const unsigned full=0xffffffffu;
  const unsigned lt=(1u<<lane)-1u;

  int   cntp[5]={0,0,0,0,0};
  float sr[5]={0,0,0,0,0}, sr2[5]={0,0,0,0,0};
  float pkreg[16];

  const float tscale = (float)(TABN-1)/(TAB_HI-TAB_LO);

  // sweep A: compute once, cache packed (kerv|sidx)
  #pragma unroll
  for(int it=0;it<16;it++){
    int j=lane+it*32;
    float dx=xi-px[j], dy=yi-py[j], dz=zi-pz[j];
    float d2=dx*dx+dy*dy+dz*dz+1e-12f;
    float d=__fsqrt_rn(d2);
    int sidx=5;
    if(j!=il && d>=5.0f)
      sidx=(d<10.f)?0:((d<20.f)?1:((d<40.f)?2:((d<80.f)?3:4)));
    float kerv=0.f;
    if(sidx<5){
      float u=(d-TAB_LO)*tscale;
      u=fminf(u,(float)(TABN-1)-1e-3f);
      int i0=(int)u; float fr=u-(float)i0;
      float t0=__ldg(&g_ktab[i0]), t1=__ldg(&g_ktab[i0+1]);
      kerv=fmaf(fr,t1-t0,t0);
      #pragma unroll
      for(int s=0;s<5;s++){
        if(sidx==s){ cntp[s]++; sr[s]+=d; sr2[s]+=d2; }
      }
    }
    pkreg[it]=__uint_as_float((__float_as_uint(kerv)&~7u)|(unsigned)sidx);
  }

  // warp-uniform counts via xor-shuffle reduce
  int cnt[5];
  #pragma unroll
  for(int s=0;s<5;s++){
    int c=cntp[s];
    #pragma unroll
    for(int o=16;o;o>>=1) c+=__shfl_xor_sync(full,c,o);
    cnt[s]=c;
  }
  int base[5]; { int run=0;
    #pragma unroll
    for(int s=0;s<5;s++){ base[s]=run; run+=cnt[s]; } }

  // sweep B: scatter cached values grouped by shell
  #pragma unroll
  for(int it=0;it<16;it++){
    unsigned pk=__float_as_uint(pkreg[it]);
    int sidx=(int)(pk&7u);
    int j=lane+it*32;
    #pragma unroll
    for(int s=0;s<5;s++){
      unsigned m=__ballot_sync(full, sidx==s);
      if(sidx==s){
        int p=base[s]+__popc(m&lt);
        ckv[p]=__uint_as_float((pk&~511u)|(unsigned)j);
      }
      base[s]+=__popc(m);
    }
  }
  __syncwarp();

  int ig=g*NATOM+il;
  float* outp=&g_shell[ig*SEIN];
  int chgrp=lane&3, jsub=lane>>2;

  // pass 2: per-shell tight segments
  int e0=0;
  #pragma unroll
  for(int q=0;q<5;q++){
    float4 acc=make_float4(0.f,0.f,0.f,0.f);
    int e1=e0+cnt[q];
    for(int e=e0+jsub;e<e1;e+=8){
      unsigned pk=__float_as_uint(ckv[e]);
      int j=(int)(pk&511u);
      float kv=__uint_as_float(pk&~511u);
      float2 raw=*((const float2*)(ssh + j*DDIM) + chgrp);
      __half2 h0=*(__half2*)&raw.x;
      __half2 h1=*(__half2*)&raw.y;
      float2 c0=__half22float2(h0);
      float2 c1=__half22float2(h1);
      acc.x=fmaf(kv,c0.x,acc.x);
      acc.y=fmaf(kv,c0.y,acc.y);
      acc.z=fmaf(kv,c1.x,acc.z);
      acc.w=fmaf(kv,c1.y,acc.w);
    }
    e0=e1;
    #pragma unroll
    for(int o=4;o<32;o<<=1){
      acc.x+=__shfl_xor_sync(full,acc.x,o);
      acc.y+=__shfl_xor_sync(full,acc.y,o);
      acc.z+=__shfl_xor_sync(full,acc.z,o);
      acc.w+=__shfl_xor_sync(full,acc.w,o);
    }
    if(lane<4){
      float inv=1.f/fmaxf((float)cnt[q],1.f);
      outp[q*19+chgrp*4+0]=acc.x*inv;
      outp[q*19+chgrp*4+1]=acc.y*inv;
      outp[q*19+chgrp*4+2]=acc.z*inv;
      outp[q*19+chgrp*4+3]=acc.w*inv;
    }
  }

  #pragma unroll
  for(int q=0;q<5;q++){
    #pragma unroll
    for(int o=16;o;o>>=1){
      sr [q]+=__shfl_xor_sync(full,sr [q],o);
      sr2[q]+=__shfl_xor_sync(full,sr2[q],o);
    }
  }
  if(lane==16){
    #pragma unroll
    for(int q=0;q<5;q++) outp[q*19+16]=(float)cnt[q];
  } else if(lane==17){
    #pragma unroll
    for(int q=0;q<5;q++) outp[q*19+17]=sr[q]/fmaxf((float)cnt[q],1.f);
  } else if(lane==18){
    #pragma unroll
    for(int q=0;q<5;q++) outp[q*19+18]=__fsqrt_rn(sr2[q]/fmaxf((float)cnt[q],1.f)+1e-12f);
  }
}

// ---------------- kernel 5: 16-atom batched shell embed + energy head ----------------
// fp16 staged weights, 256 threads, grid=512.
#define O_RSH   0                      // 16*96 = 1536
#define O_UNI   (O_RSH+16*96)          // shn 16*97=1552 + hid 16*65=1040 = 2592; ein 16*161=2576 aliases
#define O_HID   (O_UNI+16*97)
#define O_EMB   (O_UNI+2592)           // 16*17 = 272
#define O_SRC   (O_EMB+16*17+4)        // 16*16 = 256
#define O_W1H   (O_SRC+16*16)          // 95*64 half = 3040 floats
#define O_W2H   (O_W1H+3040)           // 64*16 half = 512 floats
#define O_EW1H  (O_W2H+512)            // 159*64 half = 5088 floats
#define O_EW2   (O_EW1H+5088)          // 64
#define O_LNSG  (O_EW2+64)             // 96
#define O_LNSB  (O_LNSG+96)            // 96
#define O_ELNG  (O_LNSB+96)            // 160
#define O_ELNB  (O_ELNG+160)           // 160
#define O_B1    (O_ELNB+160)           // 64
#define O_B2    (O_B1+64)              // 16
#define O_EB1   (O_B2+16)              // 64
#define FIN_SMEM ((O_EB1+64)*4)

__global__ void __launch_bounds__(256)
final_kernel2(const int* __restrict__ batch,
  const float* __restrict__ selng, const float* __restrict__ selnb,
  const float* __restrict__ sew1,  const float* __restrict__ seb1,
  const float* __restrict__ sew2,  const float* __restrict__ seb2,
  const float* __restrict__ ehlng, const float* __restrict__ ehlnb,
  const float* __restrict__ ehw1,  const float* __restrict__ ehb1,
  const float* __restrict__ ehw2,  const float* __restrict__ ehb2,
  const float* __restrict__ fg, const float* __restrict__ es, float* out)
{
  extern __shared__ float fs[];
  float* rsh = fs+O_RSH;   // stride 96
  float* shn = fs+O_UNI;   // stride 97
  float* hid = fs+O_HID;   // stride 65
  float* ein = fs+O_UNI;   // stride 161 (aliases shn+hid)
  float* h2  = fs+O_RSH;   // stride 65  (aliases rsh, reused after ein built)
  float* emb = fs+O_EMB;   // stride 17
  float* srcs= fs+O_SRC;   // stride 16
  __half* w1h = (__half*)(fs+O_W1H);
  __half* w2h = (__half*)(fs+O_W2H);
  __half* ew1h= (__half*)(fs+O_EW1H);
  float* ew2s= fs+O_EW2;

  int t=threadIdx.x;
  int abase=blockIdx.x*FMT;
  int g=abase/NATOM;

  for(int i=t;i<SEIN*HID;i+=256) w1h[i]=__float2half(sew1[i]);
  for(int i=t;i<HID*DDIM;i+=256) w2h[i]=__float2half(sew2[i]);
  for(int i=t;i<EHIN*HID;i+=256) ew1h[i]=__float2half(ehw1[i]);
  if(t<HID){ ew2s[t]=ehw2[t]; fs[O_B1+t]=seb1[t]; fs[O_EB1+t]=ehb1[t]; }
  if(t<DDIM) fs[O_B2+t]=seb2[t];
  if(t<SEIN){ fs[O_LNSG+t]=selng[t]; fs[O_LNSB+t]=selnb[t]; }
  if(t<EHIN){ fs[O_ELNG+t]=ehlng[t]; fs[O_ELNB+t]=ehlnb[t]; }
  for(int i=t;i<FMT*SEIN;i+=256){
    int a=i/SEIN, k=i-a*SEIN;
    rsh[a*96+k]=g_shell[(abase+a)*SEIN+k];
  }
  for(int i=t;i<FMT*DDIM;i+=256){
    int a=i>>4, c=i&15;
    srcs[i]=g_src[(abase+a)*DDIM+c]-g_mean[g*DDIM+c];
  }
  __syncthreads();

  int w=t>>5, lane=t&31;

  // LN(shell): 8 warps x 2 atoms
  #pragma unroll
  for(int a2=0;a2<2;a2++){
    int a=w*2+a2;
    warpLN(rsh+a*96, shn+a*97, fs+O_LNSG, fs+O_LNSB, SEIN, lane, 1.f/SEIN);
  }
  __syncthreads();

  // GEMM1: hid[16][64] = silu(shn @ w1 + b1); thread = (atom t>>4, 4 outputs t&15)
  {
    int tx=t&15, a=t>>4;
    float acc0[4];
    #pragma unroll
    for(int i=0;i<4;i++) acc0[i]=fs[O_B1+tx*4+i];
    const float2* wv2=(const float2*)w1h;   // 4 halfs per float2
    const float* A0=shn+a*97;
    #pragma unroll 5
    for(int k=0;k<SEIN;k++){
      float2 raw=wv2[k*16+tx];
      float2 w01=__half22float2(*(__half2*)&raw.x);
      float2 w23=__half22float2(*(__half2*)&raw.y);
      float v0=A0[k];
      acc0[0]=fmaf(v0,w01.x,acc0[0]); acc0[1]=fmaf(v0,w01.y,acc0[1]);
      acc0[2]=fmaf(v0,w23.x,acc0[2]); acc0[3]=fmaf(v0,w23.y,acc0[3]);
    }
    #pragma unroll
    for(int i=0;i<4;i++) hid[a*65+tx*4+i]=siluf(acc0[i]);
  }
  __syncthreads();

  // emb[16][16] = hid @ w2 + b2; thread = (atom t>>4, channel t&15)
  {
    int a=t>>4, c=t&15;
    float acc=fs[O_B2+c];
    const float* H=hid+a*65;
    #pragma unroll 8
    for(int k=0;k<HID;k++){
      float wv=__half2float(w2h[k*16+c]);
      acc=fmaf(H[k],wv,acc);
    }
    emb[a*17+c]=acc;
  }
  __syncthreads();

  for(int i=t;i<FMT*EHIN;i+=256){
    int a=i/EHIN, e=i-a*EHIN;
    float v;
    if(e<16){ v=srcs[a*16+e]; }
    else if(e<32){ v=emb[a*17+(e-16)]; }
    else if(e<48){ v=srcs[a*16+(e-32)]*emb[a*17+(e-32)]; }
    else if(e<64){ v=srcs[a*16+(e-48)]-emb[a*17+(e-48)]; }
    else { v=rsh[a*96+(e-64)]; }
    ein[a*161+e]=v;
  }
  __syncthreads();

  #pragma unroll
  for(int a2=0;a2<2;a2++){
    int a=w*2+a2;
    warpLN(ein+a*161, ein+a*161, fs+O_ELNG, fs+O_ELNB, EHIN, lane, 1.f/EHIN);
  }
  __syncthreads();

  // GEMM2: h2[16][64] = silu(ein @ ew1 + eb1)
  {
    int tx=t&15, a=t>>4;
    float acc0[4];
    #pragma unroll
    for(int i=0;i<4;i++) acc0[i]=fs[O_EB1+tx*4+i];
    const float2* wv2=(const float2*)ew1h;
    const float* A0=ein+a*161;
    #pragma unroll 3
    for(int k=0;k<EHIN;k++){
      float2 raw=wv2[k*16+tx];
      float2 w01=__half22float2(*(__half2*)&raw.x);
      float2 w23=__half22float2(*(__half2*)&raw.y);
      float v0=A0[k];
      acc0[0]=fmaf(v0,w01.x,acc0[0]); acc0[1]=fmaf(v0,w01.y,acc0[1]);
      acc0[2]=fmaf(v0,w23.x,acc0[2]); acc0[3]=fmaf(v0,w23.y,acc0[3]);
    }
    __syncthreads();   // ein reads done before h2 (aliases rsh) written
    #pragma unroll
    for(int i=0;i<4;i++) h2[a*65+tx*4+i]=siluf(acc0[i]);
  }
  __syncthreads();

  float scale = tanhf(fg[0])*__expf(es[0]);
  float eb2 = ehb2[0];
  #pragma unroll
  for(int a2=0;a2<2;a2++){
    int a=w*2+a2;
    float p=h2[a*65+lane]*ew2s[lane]+h2[a*65+lane+32]*ew2s[lane+32];
    #pragma unroll
    for(int o=16;o;o>>=1) p+=__shfl_xor_sync(0xffffffffu,p,o);
    if(lane==0){
      float pa=(p+eb2)*scale;
      atomicAdd(&out[batch[abase+a]],pa);
    }
  }
}

extern "C" void kernel_launch(void* const* d_in, const int* in_sizes, int n_in,
                              void* d_out, int out_size) {
  const float* x   = (const float*)d_in[0];
  const float* pos = (const float*)d_in[1];
  const int* batch = (const int*)d_in[2];
  int off = (in_sizes[3]==1) ? 4 : 3;
  const float* in_ln_g = (const float*)d_in[off+0];
  const float* in_ln_b = (const float*)d_in[off+1];
  const float* src_w1  = (const float*)d_in[off+2];
  const float* src_b1  = (const float*)d_in[off+3];
  const float* src_w2  = (const float*)d_in[off+4];
  const float* src_b2  = (const float*)d_in[off+5];
  const float* src_ln_g= (const float*)d_in[off+6];
  const float* src_ln_b= (const float*)d_in[off+7];
  const float* se_ln_g = (const float*)d_in[off+8];
  const float* se_ln_b = (const float*)d_in[off+9];
  const float* se_w1   = (const float*)d_in[off+10];
  const float* se_b1   = (const float*)d_in[off+11];
  const float* se_w2   = (const float*)d_in[off+12];
  const float* se_b2   = (const float*)d_in[off+13];
  const float* eh_ln_g = (const float*)d_in[off+14];
  const float* eh_ln_b = (const float*)d_in[off+15];
  const float* eh_w1   = (const float*)d_in[off+16];
  const float* eh_b1   = (const float*)d_in[off+17];
  const float* eh_w2   = (const float*)d_in[off+18];
  const float* eh_b2   = (const float*)d_in[off+19];
  const float* k_screen= (const float*)d_in[off+20];
  const float* kg_w1   = (const float*)d_in[off+21];
  const float* kg_b1   = (const float*)d_in[off+22];
  const float* kg_w2   = (const float*)d_in[off+23];
  const float* kg_b2   = (const float*)d_in[off+24];
  const float* far_gate= (const float*)d_in[off+25];
  const float* en_scale= (const float*)d_in[off+26];
  float* out = (float*)d_out;

  const int pair_smem = (3*NATOM)*4 + NATOM*DDIM*2 + APB*NATOM*4; // 38912B
  cudaFuncSetAttribute(pair_kernel, cudaFuncAttributeMaxDynamicSharedMemorySize, pair_smem);
  cudaFuncSetAttribute(final_kernel2, cudaFuncAttributeMaxDynamicSharedMemorySize, FIN_SMEM);

  src_kernel<<<MTOT + TABN/FDIM, FDIM>>>(x, in_ln_g, in_ln_b, src_w1, src_b1, src_w2,
                            src_b2, src_ln_g, src_ln_b,
                            kg_w1, kg_b1, kg_w2, kg_b2, k_screen, out, out_size);
  mean_kernel<<<BGR,256>>>();
  pair_kernel<<<NBLK,256,pair_smem>>>(pos);
  final_kernel2<<<MTOT/FMT,256,FIN_SMEM>>>(batch, se_ln_g, se_ln_b, se_w1, se_b1,
                             se_w2, se_b2, eh_ln_g, eh_ln_b, eh_w1, eh_b1, eh_w2, eh_b2,
                             far_gate, en_scale, out);
}